// round 15
// baseline (speedup 1.0000x reference)
#include <cuda_runtime.h>
#include <cuda_fp16.h>
#include <math.h>
#include <stdint.h>

#define BATCH 8
#define NTOK 1024
#define DIM 768
#define HEADS 12
#define HD 64
#define MTOT (BATCH * NTOK)       // 8192
#define QKVN (3 * DIM)            // 2304

// ---------------- scratch ----------------
__device__ __half g_h16[MTOT * DIM];
__device__ __half g_qkv16[MTOT * QKVN];
__device__ __half g_o16[MTOT * DIM];
__device__ float  g_x1[MTOT * DIM];
__device__ __half g_h2_16[MTOT * DIM];
__device__ __half g_a16[MTOT * DIM];
__device__ __half g_wqkv16[DIM * QKVN];
__device__ __half g_wproj16[DIM * DIM];
__device__ __half g_wfc1_16[DIM * DIM];
__device__ __half g_wfc2_16[DIM * DIM];

// ---------------- helpers ----------------
__device__ __forceinline__ uint32_t smem_u32(const void* p) {
    return (uint32_t)__cvta_generic_to_shared(p);
}
__device__ __forceinline__ void cp16(uint32_t dst, const void* src) {
    asm volatile("cp.async.cg.shared.global [%0], [%1], 16;\n" :: "r"(dst), "l"(src));
}
#define CP_COMMIT()  asm volatile("cp.async.commit_group;\n" ::: "memory")
#define CP_WAIT(N)   asm volatile("cp.async.wait_group %0;\n" :: "n"(N) : "memory")

__device__ __forceinline__ void ldsm_x4(uint32_t& r0, uint32_t& r1, uint32_t& r2, uint32_t& r3,
                                        uint32_t addr) {
    asm volatile("ldmatrix.sync.aligned.m8n8.x4.shared.b16 {%0,%1,%2,%3}, [%4];"
                 : "=r"(r0), "=r"(r1), "=r"(r2), "=r"(r3) : "r"(addr));
}
__device__ __forceinline__ void ldsm_x4_t(uint32_t& r0, uint32_t& r1, uint32_t& r2, uint32_t& r3,
                                          uint32_t addr) {
    asm volatile("ldmatrix.sync.aligned.m8n8.x4.trans.shared.b16 {%0,%1,%2,%3}, [%4];"
                 : "=r"(r0), "=r"(r1), "=r"(r2), "=r"(r3) : "r"(addr));
}

__device__ __forceinline__ void mma_f16(float& c0, float& c1, float& c2, float& c3,
                                        uint32_t a0, uint32_t a1, uint32_t a2, uint32_t a3,
                                        uint32_t b0, uint32_t b1) {
    asm volatile(
        "mma.sync.aligned.m16n8k16.row.col.f32.f16.f16.f32 "
        "{%0,%1,%2,%3}, {%4,%5,%6,%7}, {%8,%9}, {%0,%1,%2,%3};\n"
        : "+f"(c0), "+f"(c1), "+f"(c2), "+f"(c3)
        : "r"(a0), "r"(a1), "r"(a2), "r"(a3), "r"(b0), "r"(b1));
}

// fast GELU (tanh form, ex2-based)
__device__ __forceinline__ float gelu_fast(float v) {
    float u = 0.7978845608f * (v + 0.044715f * v * v * v);
    float e;
    asm("ex2.approx.f32 %0, %1;" : "=f"(e) : "f"(u * 2.8853900817f));  // exp(2u)
    float th = 1.f - 2.f * __fdividef(1.f, e + 1.f);
    return 0.5f * v * (1.f + th);
}

// ---------------- fp32 -> fp16 weight conversions (split) ----------------
#define S_QKV (DIM * QKVN / 4)    // 442368 float4s
#define S_SQ  (DIM * DIM / 4)     // 147456
#define S_RST (3 * S_SQ)

__global__ void __launch_bounds__(256)
f2h_qkv(const float* __restrict__ w, __half* __restrict__ o) {
    int i = blockIdx.x * 256 + threadIdx.x;
    if (i >= S_QKV) return;
    float4 v = ((const float4*)w)[i];
    __half2 a = __floats2half2_rn(v.x, v.y);
    __half2 b = __floats2half2_rn(v.z, v.w);
    ((uint2*)o)[i] = make_uint2(*(uint32_t*)&a, *(uint32_t*)&b);
}

__global__ void __launch_bounds__(256)
f2h_rest(const float* __restrict__ w1, const float* __restrict__ w2,
         const float* __restrict__ w3,
         __half* __restrict__ o1, __half* __restrict__ o2, __half* __restrict__ o3) {
    int i = blockIdx.x * 256 + threadIdx.x;
    if (i >= S_RST) return;
    const float* src; __half* dst; int j;
    if (i < S_SQ)          { src = w1; dst = o1; j = i; }
    else if (i < 2 * S_SQ) { src = w2; dst = o2; j = i - S_SQ; }
    else                   { src = w3; dst = o3; j = i - 2 * S_SQ; }
    float4 v = ((const float4*)src)[j];
    __half2 a = __floats2half2_rn(v.x, v.y);
    __half2 b = __floats2half2_rn(v.z, v.w);
    ((uint2*)dst)[j] = make_uint2(*(uint32_t*)&a, *(uint32_t*)&b);
}

// ---------------- LayerNorm: warp per row ----------------
__global__ void __launch_bounds__(256)
ln_kernel(const float* __restrict__ x, const float* __restrict__ g,
          const float* __restrict__ b, __half* __restrict__ y) {
    int wid = threadIdx.x >> 5, lane = threadIdx.x & 31;
    int row = blockIdx.x * 8 + wid;
    const float4* xr = (const float4*)(x + (size_t)row * DIM);
    const float4* gp = (const float4*)g;
    const float4* bp = (const float4*)b;

    float4 v[6];
    float s = 0.f;
    #pragma unroll
    for (int i = 0; i < 6; i++) {
        v[i] = xr[lane + 32 * i];
        s += v[i].x + v[i].y + v[i].z + v[i].w;
    }
    #pragma unroll
    for (int o = 16; o; o >>= 1) s += __shfl_xor_sync(0xFFFFFFFFu, s, o);
    float mu = s * (1.0f / DIM);

    float vs = 0.f;
    #pragma unroll
    for (int i = 0; i < 6; i++) {
        float dx = v[i].x - mu, dy = v[i].y - mu, dz = v[i].z - mu, dw = v[i].w - mu;
        vs += dx * dx + dy * dy + dz * dz + dw * dw;
    }
    #pragma unroll
    for (int o = 16; o; o >>= 1) vs += __shfl_xor_sync(0xFFFFFFFFu, vs, o);
    float inv = rsqrtf(vs * (1.0f / DIM) + 1e-5f);

    uint2* yr = (uint2*)(y + (size_t)row * DIM);
    #pragma unroll
    for (int i = 0; i < 6; i++) {
        float4 gv = gp[lane + 32 * i];
        float4 bv = bp[lane + 32 * i];
        float o0 = (v[i].x - mu) * inv * gv.x + bv.x;
        float o1 = (v[i].y - mu) * inv * gv.y + bv.y;
        float o2 = (v[i].z - mu) * inv * gv.z + bv.z;
        float o3 = (v[i].w - mu) * inv * gv.w + bv.w;
        __half2 ha = __floats2half2_rn(o0, o1);
        __half2 hb = __floats2half2_rn(o2, o3);
        yr[lane + 32 * i] = make_uint2(*(uint32_t*)&ha, *(uint32_t*)&hb);
    }
}

// ---------------- fp16 GEMM A: 128x128 tile, 4 warps (2x2), 64x64 warp tile ----------
#define G7_AH (128 * 40)
#define G7_BH (32 * 136)
#define G7_ST ((G7_AH + G7_BH) * 2)
#define GEMM7_SMEM (3 * G7_ST)

template <int ACT, bool HAS_BIAS, bool HAS_RES, bool OUT_HALF>
__global__ void __launch_bounds__(128, 2)
gemm10(const __half* __restrict__ A, const __half* __restrict__ Bm,
       const float* __restrict__ bias, const float* __restrict__ resid,
       float* __restrict__ C, __half* __restrict__ Ch, int N, int K) {
    extern __shared__ char smc[];

    int tid = threadIdx.x;
    int wid = tid >> 5, lane = tid & 31;
    int g = lane >> 2, t4 = lane & 3;
    int wm = wid & 1, wn = wid >> 1;
    int m0 = blockIdx.y * 128, n0 = blockIdx.x * 128;
    int rb = wm * 64, cb = wn * 64;

    int a_row = lane & 15, a_kh = (lane >> 4) * 8;
    int b_k = ((lane >> 3) & 1) * 8 + (lane & 7);
    int b_n = (lane >> 4) * 8;

    float acc[4][8][4];
    #pragma unroll
    for (int i = 0; i < 4; i++)
        #pragma unroll
        for (int j = 0; j < 8; j++)
            #pragma unroll
            for (int q = 0; q < 4; q++) acc[i][j][q] = 0.f;

    auto load_stage = [&](int t, int s) {
        __half* As = (__half*)(smc + s * G7_ST);
        __half* Bs = As + G7_AH;
        int kt = t << 5;
        #pragma unroll
        for (int i = 0; i < 4; i++) {
            int ch = tid + 128 * i;
            int r = ch >> 2, c = ch & 3;
            cp16(smem_u32(&As[r * 40 + c * 8]), A + (size_t)(m0 + r) * K + kt + c * 8);
        }
        #pragma unroll
        for (int i = 0; i < 4; i++) {
            int ch = tid + 128 * i;
            int r = ch >> 4, c = ch & 15;
            cp16(smem_u32(&Bs[r * 136 + c * 8]), Bm + (size_t)(kt + r) * N + n0 + c * 8);
        }
        CP_COMMIT();
    };

    const int T = K >> 5;
    load_stage(0, 0);
    load_stage(1, 1);

    for (int t = 0; t < T; t++) {
        int s = t % 3;
        if (t + 1 < T) { CP_WAIT(1); } else { CP_WAIT(0); }
        __syncthreads();
        if (t + 2 < T) load_stage(t + 2, (t + 2) % 3);

        const __half* As = (const __half*)(smc + s * G7_ST);
        const __half* Bs = As + G7_AH;

        #pragma unroll
        for (int ks = 0; ks < 2; ks++) {
            uint32_t af[4][4];
            #pragma unroll
            for (int mi = 0; mi < 4; mi++)
                ldsm_x4(af[mi][0], af[mi][1], af[mi][2], af[mi][3],
                        smem_u32(&As[(rb + mi * 16 + a_row) * 40 + ks * 16 + a_kh]));
            uint32_t bf[8][2];
            #pragma unroll
            for (int njp = 0; njp < 4; njp++)
                ldsm_x4_t(bf[njp * 2][0], bf[njp * 2][1], bf[njp * 2 + 1][0], bf[njp * 2 + 1][1],
                          smem_u32(&Bs[(ks * 16 + b_k) * 136 + cb + njp * 16 + b_n]));
            #pragma unroll
            for (int mi = 0; mi < 4; mi++)
                #pragma unroll
                for (int nj = 0; nj < 8; nj++)
                    mma_f16(acc[mi][nj][0], acc[mi][nj][1], acc[mi][nj][2], acc[mi][nj][3],
                            af[mi][0], af[mi][1], af[mi][2], af[mi][3],
                            bf[nj][0], bf[nj][1]);
        }
    }

    #pragma unroll
    for (int mi = 0; mi < 4; mi++) {
        #pragma unroll
        for (int half_ = 0; half_ < 2; half_++) {
            int r = m0 + rb + mi * 16 + half_ * 8 + g;
            const float* rrow = HAS_RES ? resid + (size_t)r * N : nullptr;
            #pragma unroll
            for (int nj = 0; nj < 8; nj++) {
                int c = n0 + cb + nj * 8 + t4 * 2;
                float v0 = acc[mi][nj][half_ * 2 + 0];
                float v1 = acc[mi][nj][half_ * 2 + 1];
                if (HAS_BIAS) { v0 += bias[c]; v1 += bias[c + 1]; }
                if (HAS_RES)  { v0 += rrow[c]; v1 += rrow[c + 1]; }
                if (ACT == 1) { v0 = gelu_fast(v0); v1 = gelu_fast(v1); }
                if (OUT_HALF) {
                    __half2 hv = __floats2half2_rn(v0, v1);
                    *(uint32_t*)(Ch + (size_t)r * N + c) = *(uint32_t*)&hv;
                } else {
                    *(float2*)(C + (size_t)r * N + c) = make_float2(v0, v1);
                }
            }
        }
    }
}

// ---------------- fp16 GEMM B: 128x64 tile, 4 warps (2x2), 64x32 warp tile, 3 CTA/SM ----
#define GN_AH (128 * 40)
#define GN_BH (32 * 72)
#define GN_ST ((GN_AH + GN_BH) * 2)
#define GEMMN64_SMEM (3 * GN_ST)

template <int ACT, bool HAS_BIAS, bool HAS_RES, bool OUT_HALF>
__global__ void __launch_bounds__(128, 3)
gemm_n64(const __half* __restrict__ A, const __half* __restrict__ Bm,
         const float* __restrict__ bias, const float* __restrict__ resid,
         float* __restrict__ C, __half* __restrict__ Ch, int N, int K) {
    extern __shared__ char smc[];

    int tid = threadIdx.x;
    int wid = tid >> 5, lane = tid & 31;
    int g = lane >> 2, t4 = lane & 3;
    int wm = wid & 1, wn = wid >> 1;
    int m0 = blockIdx.y * 128, n0 = blockIdx.x * 64;
    int rb = wm * 64, cb = wn * 32;

    int a_row = lane & 15, a_kh = (lane >> 4) * 8;
    int b_k = ((lane >> 3) & 1) * 8 + (lane & 7);
    int b_n = (lane >> 4) * 8;

    float acc[4][4][4];
    #pragma unroll
    for (int i = 0; i < 4; i++)
        #pragma unroll
        for (int j = 0; j < 4; j++)
            #pragma unroll
            for (int q = 0; q < 4; q++) acc[i][j][q] = 0.f;

    auto load_stage = [&](int t, int s) {
        __half* As = (__half*)(smc + s * GN_ST);
        __half* Bs = As + GN_AH;
        int kt = t << 5;
        #pragma unroll
        for (int i = 0; i < 4; i++) {
            int ch = tid + 128 * i;
            int r = ch >> 2, c = ch & 3;
            cp16(smem_u32(&As[r * 40 + c * 8]), A + (size_t)(m0 + r) * K + kt + c * 8);
        }
        #pragma unroll
        for (int i = 0; i < 2; i++) {
            int ch = tid + 128 * i;
            int r = ch >> 3, c = ch & 7;
            cp16(smem_u32(&Bs[r * 72 + c * 8]), Bm + (size_t)(kt + r) * N + n0 + c * 8);
        }
        CP_COMMIT();
    };

    const int T = K >> 5;
    load_stage(0, 0);
    load_stage(1, 1);

    for (int t = 0; t < T; t++) {
        int s = t % 3;
        if (t + 1 < T) { CP_WAIT(1); } else { CP_WAIT(0); }
        __syncthreads();
        if (t + 2 < T) load_stage(t + 2, (t + 2) % 3);

        const __half* As = (const __half*)(smc + s * GN_ST);
        const __half* Bs = As + GN_AH;

        #pragma unroll
        for (int ks = 0; ks < 2; ks++) {
            uint32_t af[4][4];
            #pragma unroll
            for (int mi = 0; mi < 4; mi++)
                ldsm_x4(af[mi][0], af[mi][1], af[mi][2], af[mi][3],
                        smem_u32(&As[(rb + mi * 16 + a_row) * 40 + ks * 16 + a_kh]));
            uint32_t bf[4][2];
            #pragma unroll
            for (int njp = 0; njp < 2; njp++)
                ldsm_x4_t(bf[njp * 2][0], bf[njp * 2][1], bf[njp * 2 + 1][0], bf[njp * 2 + 1][1],
                          smem_u32(&Bs[(ks * 16 + b_k) * 72 + cb + njp * 16 + b_n]));
            #pragma unroll
            for (int mi = 0; mi < 4; mi++)
                #pragma unroll
                for (int nj = 0; nj < 4; nj++)
                    mma_f16(acc[mi][nj][0], acc[mi][nj][1], acc[mi][nj][2], acc[mi][nj][3],
                            af[mi][0], af[mi][1], af[mi][2], af[mi][3],
                            bf[nj][0], bf[nj][1]);
        }
    }

    #pragma unroll
    for (int mi = 0; mi < 4; mi++) {
        #pragma unroll
        for (int half_ = 0; half_ < 2; half_++) {
            int r = m0 + rb + mi * 16 + half_ * 8 + g;
            const float* rrow = HAS_RES ? resid + (size_t)r * N : nullptr;
            #pragma unroll
            for (int nj = 0; nj < 4; nj++) {
                int c = n0 + cb + nj * 8 + t4 * 2;
                float v0 = acc[mi][nj][half_ * 2 + 0];
                float v1 = acc[mi][nj][half_ * 2 + 1];
                if (HAS_BIAS) { v0 += bias[c]; v1 += bias[c + 1]; }
                if (HAS_RES)  { v0 += rrow[c]; v1 += rrow[c + 1]; }
                if (ACT == 1) { v0 = gelu_fast(v0); v1 = gelu_fast(v1); }
                if (OUT_HALF) {
                    __half2 hv = __floats2half2_rn(v0, v1);
                    *(uint32_t*)(Ch + (size_t)r * N + c) = *(uint32_t*)&hv;
                } else {
                    *(float2*)(C + (size_t)r * N + c) = make_float2(v0, v1);
                }
            }
        }
    }
}

// ---------------- fp16 flash attention: 4 warps x 32 q-rows, single barrier/iter ----------
#define AK_ST 72
#define ATTN13_SMEM (2 * 64 * AK_ST * 2 * 2 + 1024 * 2)

__global__ void __launch_bounds__(128, 2)
attn13(const __half* __restrict__ qkv, const int* __restrict__ mask,
       __half* __restrict__ o_out) {
    extern __shared__ char smc[];
    __half* KsB = (__half*)smc;
    __half* VsB = KsB + 2 * 64 * AK_ST;
    __half* Mkh = VsB + 2 * 64 * AK_ST;

    int h = blockIdx.y, b = blockIdx.z;
    int tid = threadIdx.x;
    int wid = tid >> 5, lane = tid & 31;
    int g = lane >> 2, t4 = lane & 3;
    int rb0 = wid * 32;
    int qrow0 = blockIdx.x * 128;

    int kA_n = (lane >> 4) * 8 + (lane & 7);
    int kA_d = ((lane >> 3) & 1) * 8;
    int vT_k = ((lane >> 3) & 1) * 8 + (lane & 7);
    int vT_d = (lane >> 4) * 8;

    auto stage_kv = [&](int t, int s) {
        __half* Ks = KsB + s * 64 * AK_ST;
        __half* Vs = VsB + s * 64 * AK_ST;
        int kt = t * 64;
        #pragma unroll
        for (int it = 0; it < 4; it++) {
            int idx = tid + 128 * it;
            int r = idx >> 3, c = idx & 7;
            const __half* kp = qkv + (size_t)(b * NTOK + kt + r) * QKVN + DIM + h * HD + c * 8;
            cp16(smem_u32(&Ks[r * AK_ST + c * 8]), kp);
            cp16(smem_u32(&Vs[r * AK_ST + c * 8]), kp + DIM);
        }
        CP_COMMIT();
    };

    // kick off tile 0 ASAP, then overlap Q/mask loads with it
    stage_kv(0, 0);

    #pragma unroll
    for (int i = 0; i < 8; i++)
        Mkh[tid + 128 * i] = __int2half_rn(mask[b * NTOK + tid + 128 * i]);

    const __half2 C2 = __floats2half2_rn(0.18033688f, 0.18033688f);  // 0.125*log2(e)

    uint32_t qf[2][4][4];
    #pragma unroll
    for (int r = 0; r < 2; r++) {
        const uint32_t* qlo = (const uint32_t*)(qkv + (size_t)(b * NTOK + qrow0 + rb0 + r * 16 + g) * QKVN + h * HD);
        const uint32_t* qhi = (const uint32_t*)(qkv + (size_t)(b * NTOK + qrow0 + rb0 + r * 16 + g + 8) * QKVN + h * HD);
        #pragma unroll
        for (int kc = 0; kc < 4; kc++) {
            qf[r][kc][0] = qlo[kc * 8 + t4];
            qf[r][kc][1] = qhi[kc * 8 + t4];
            qf[r][kc][2] = qlo[kc * 8 + t4 + 4];
            qf[r][kc][3] = qhi[kc * 8 + t4 + 4];
        }
    }

    float oacc[2][8][4];
    #pragma unroll
    for (int r = 0; r < 2; r++)
        #pragma unroll
        for (int i = 0; i < 8; i++)
            #pragma unroll
            for (int q = 0; q < 4; q++) oacc[r][i][q] = 0.f;
    float lsum[2][2] = {{0.f, 0.f}, {0.f, 0.f}};

    const int NT = NTOK / 64;

    for (int t = 0; t < NT; t++) {
        int s = t & 1;
        // single barrier: all warps finished previous compute (slot s^1 free);
        // at t==0 it also publishes the Mkh stores block-wide.
        __syncthreads();
        if (t + 1 < NT) { stage_kv(t + 1, s ^ 1); CP_WAIT(1); }
        else            { CP_WAIT(0); }

        const __half* Ks = KsB + s * 64 * AK_ST;
        const __half* Vs = VsB + s * 64 * AK_ST;

        // ---- S = Q @ K^T ----
        float sc[2][8][4];
        #pragma unroll
        for (int r = 0; r < 2; r++)
            #pragma unroll
            for (int nj = 0; nj < 8; nj++)
                #pragma unroll
                for (int q = 0; q < 4; q++) sc[r][nj][q] = 0.f;
        #pragma unroll
        for (int kc = 0; kc < 4; kc++) {
            uint32_t kb[8][2];
            #pragma unroll
            for (int njp = 0; njp < 4; njp++)
                ldsm_x4(kb[njp * 2][0], kb[njp * 2][1], kb[njp * 2 + 1][0], kb[njp * 2 + 1][1],
                        smem_u32(&Ks[(njp * 16 + kA_n) * AK_ST + kc * 16 + kA_d]));
            #pragma unroll
            for (int r = 0; r < 2; r++)
                #pragma unroll
                for (int nj = 0; nj < 8; nj++)
                    mma_f16(sc[r][nj][0], sc[r][nj][1], sc[r][nj][2], sc[r][nj][3],
                            qf[r][kc][0], qf[r][kc][1], qf[r][kc][2], qf[r][kc][3],
                            kb[nj][0], kb[nj][1]);
        }

        // ---- P = ex2.f16x2(S * 0.125*log2e) * mask, in registers ----
        uint32_t pa[2][8][2];
        const __half* mkt = Mkh + t * 64;
        #pragma unroll
        for (int r = 0; r < 2; r++) {
            #pragma unroll
            for (int nj = 0; nj < 8; nj++) {
                uint32_t mkp = *(uint32_t*)&mkt[nj * 8 + 2 * t4];
                __half2 s01 = __floats2half2_rn(sc[r][nj][0], sc[r][nj][1]);
                __half2 s23 = __floats2half2_rn(sc[r][nj][2], sc[r][nj][3]);
                s01 = __hmul2(s01, C2);
                s23 = __hmul2(s23, C2);
                uint32_t e01, e23;
                asm("ex2.approx.f16x2 %0, %1;" : "=r"(e01) : "r"(*(uint32_t*)&s01));
                asm("ex2.approx.f16x2 %0, %1;" : "=r"(e23) : "r"(*(uint32_t*)&s23));
                __half2 p01 = __hmul2(*(__half2*)&e01, *(__half2*)&mkp);
                __half2 p23 = __hmul2(*(__half2*)&e23, *(__half2*)&mkp);
                float2 f01 = __half22float2(p01), f23 = __half22float2(p23);
                lsum[r][0] += f01.x + f01.y;
                lsum[r][1] += f23.x + f23.y;
                pa[r][nj][0] = *(uint32_t*)&p01;
                pa[r][nj][1] = *(uint32_t*)&p23;
            }
        }

        // ---- O += P @ V ----
        #pragma unroll
        for (int kc = 0; kc < 4; kc++) {
            uint32_t vb[8][2];
            #pragma unroll
            for (int njp = 0; njp < 4; njp++)
                ldsm_x4_t(vb[njp * 2][0], vb[njp * 2][1], vb[njp * 2 + 1][0], vb[njp * 2 + 1][1],
                          smem_u32(&Vs[(kc * 16 + vT_k) * AK_ST + njp * 16 + vT_d]));
            #pragma unroll
            for (int r = 0; r < 2; r++) {
                uint32_t a0 = pa[r][2 * kc][0],     a1 = pa[r][2 * kc][1];
                uint32_t a2 = pa[r][2 * kc + 1][0], a3 = pa[r][2 * kc + 1][1];
                #pragma unroll
                for (int nj = 0; nj < 8; nj++)
                    mma_f16(oacc[r][nj][0], oacc[r][nj][1], oacc[r][nj][2], oacc[r][nj][3],
                            a0, a1, a2, a3, vb[nj][0], vb[nj][1]);
            }
        }
    }

    #pragma unroll
    for (int r = 0; r < 2; r++) {
        float llo = lsum[r][0], lhi = lsum[r][1];
        llo += __shfl_xor_sync(0xFFFFFFFFu, llo, 1);
        llo += __shfl_xor_sync(0xFFFFFFFFu, llo, 2);
        lhi += __shfl_xor_sync(0xFFFFFFFFu, lhi, 1);
        lhi += __shfl_xor_sync(0xFFFFFFFFu, lhi, 2);
        float inv_lo = 1.0f / llo, inv_hi = 1.0f / lhi;

        __half* olo = o_out + (size_t)(b * NTOK + qrow0 + rb0 + r * 16 + g) * DIM + h * HD;
        __half* ohi = olo + (size_t)8 * DIM;
        #pragma unroll
        for (int nj = 0; nj < 8; nj++) {
            int c = nj * 8 + 2 * t4;
            __half2 va = __floats2half2_rn(oacc[r][nj][0] * inv_lo, oacc[r][nj][1] * inv_lo);
            __half2 vb2 = __floats2half2_rn(oacc[r][nj][2] * inv_hi, oacc[r][nj][3] * inv_hi);
            *(uint32_t*)(olo + c) = *(uint32_t*)&va;
            *(uint32_t*)(ohi + c) = *(uint32_t*)&vb2;
        }
    }
}

// ---------------- launcher ----------------
extern "C" void kernel_launch(void* const* d_in, const int* in_sizes, int n_in,
                              void* d_out, int out_size) {
    const float* x      = (const float*)d_in[0];
    const int*   mask   = (const int*)  d_in[1];
    const float* g1     = (const float*)d_in[2];
    const float* b1     = (const float*)d_in[3];
    const float* w_qkv  = (const float*)d_in[4];
    const float* w_proj = (const float*)d_in[5];
    const float* b_proj = (const float*)d_in[6];
    const float* g2     = (const float*)d_in[7];
    const float* b2     = (const float*)d_in[8];
    const float* w_fc1  = (const float*)d_in[9];
    const float* b_fc1  = (const float*)d_in[10];
    const float* w_fc2  = (const float*)d_in[11];
    const float* b_fc2  = (const float*)d_in[12];
    float* out = (float*)d_out;

    static bool init_done = false;
    static __half *h16, *qkv16, *o16, *h2_16, *a16;
    static __half *wqkv16, *wproj16, *wfc1_16, *wfc2_16;
    static float *x1_p;
    static cudaStream_t s2;
    static cudaEvent_t evA, evB;
    if (!init_done) {
        cudaGetSymbolAddress((void**)&h16, g_h16);
        cudaGetSymbolAddress((void**)&qkv16, g_qkv16);
        cudaGetSymbolAddress((void**)&o16, g_o16);
        cudaGetSymbolAddress((void**)&h2_16, g_h2_16);
        cudaGetSymbolAddress((void**)&a16, g_a16);
        cudaGetSymbolAddress((void**)&wqkv16, g_wqkv16);
        cudaGetSymbolAddress((void**)&wproj16, g_wproj16);
        cudaGetSymbolAddress((void**)&wfc1_16, g_wfc1_16);
        cudaGetSymbolAddress((void**)&wfc2_16, g_wfc2_16);
        cudaGetSymbolAddress((void**)&x1_p, g_x1);
        cudaStreamCreateWithFlags(&s2, cudaStreamNonBlocking);
        cudaEventCreateWithFlags(&evA, cudaEventDisableTiming);
        cudaEventCreateWithFlags(&evB, cudaEventDisableTiming);
        cudaFuncSetAttribute(attn13, cudaFuncAttributeMaxDynamicSharedMemorySize, ATTN13_SMEM);
        cudaFuncSetAttribute(gemm10<0, false, false, true>,
                             cudaFuncAttributeMaxDynamicSharedMemorySize, GEMM7_SMEM);
        cudaFuncSetAttribute(gemm_n64<0, true, true, false>,
                             cudaFuncAttributeMaxDynamicSharedMemorySize, GEMMN64_SMEM);
        cudaFuncSetAttribute(gemm_n64<1, true, false, true>,
                             cudaFuncAttributeMaxDynamicSharedMemorySize, GEMMN64_SMEM);
        init_done = true;
    }

    // fork: convert the 3 square weights on s2, hidden under qkv+attn (~200 us window)
    cudaEventRecord(evA, 0);
    cudaStreamWaitEvent(s2, evA, 0);
    f2h_rest<<<(S_RST + 255) / 256, 256, 0, s2>>>(w_proj, w_fc1, w_fc2,
                                                  wproj16, wfc1_16, wfc2_16);
    cudaEventRecord(evB, s2);

    // main: LN1, wqkv conversion (needed immediately), qkv, attention
    ln_kernel<<<MTOT / 8, 256>>>(x, g1, b1, h16);
    f2h_qkv<<<(S_QKV + 255) / 256, 256>>>(w_qkv, wqkv16);

    gemm10<0, false, false, true><<<dim3(QKVN / 128, MTOT / 128), 128, GEMM7_SMEM>>>(
        h16, wqkv16, nullptr, nullptr, nullptr, qkv16, QKVN, DIM);

    attn13<<<dim3(NTOK / 128, HEADS, BATCH), 128, ATTN13_SMEM>>>(qkv16, mask, o16);

    // join: square weights must be converted before proj
    cudaStreamWaitEvent(0, evB, 0);

    gemm_n64<0, true, true, false><<<dim3(DIM / 64, MTOT / 128), 128, GEMMN64_SMEM>>>(
        o16, wproj16, b_proj, x, x1_p, nullptr, DIM, DIM);

    ln_kernel<<<MTOT / 8, 256>>>(x1_p, g2, b2, h2_16);

    gemm_n64<1, true, false, true><<<dim3(DIM / 64, MTOT / 128), 128, GEMMN64_SMEM>>>(
        h2_16, wfc1_16, b_fc1, nullptr, nullptr, a16, DIM, DIM);

    gemm_n64<0, true, true, false><<<dim3(DIM / 64, MTOT / 128), 128, GEMMN64_SMEM>>>(
        a16, wfc2_16, b_fc2, x1_p, out, nullptr, DIM, DIM);
}

// round 16
// speedup vs baseline: 1.0112x; 1.0112x over previous
#include <cuda_runtime.h>
#include <cuda_fp16.h>
#include <math.h>
#include <stdint.h>

#define BATCH 8
#define NTOK 1024
#define DIM 768
#define HEADS 12
#define HD 64
#define MTOT (BATCH * NTOK)       // 8192
#define QKVN (3 * DIM)            // 2304

// ---------------- scratch ----------------
__device__ __half g_h16[MTOT * DIM];
__device__ __half g_qkv16[MTOT * QKVN];
__device__ __half g_o16[MTOT * DIM];
__device__ float  g_x1[MTOT * DIM];
__device__ __half g_h2_16[MTOT * DIM];
__device__ __half g_a16[MTOT * DIM];
__device__ __half g_wqkv16[DIM * QKVN];
__device__ __half g_wproj16[DIM * DIM];
__device__ __half g_wfc1_16[DIM * DIM];
__device__ __half g_wfc2_16[DIM * DIM];

// ---------------- helpers ----------------
__device__ __forceinline__ uint32_t smem_u32(const void* p) {
    return (uint32_t)__cvta_generic_to_shared(p);
}
__device__ __forceinline__ void cp16(uint32_t dst, const void* src) {
    asm volatile("cp.async.cg.shared.global [%0], [%1], 16;\n" :: "r"(dst), "l"(src));
}
#define CP_COMMIT()  asm volatile("cp.async.commit_group;\n" ::: "memory")
#define CP_WAIT(N)   asm volatile("cp.async.wait_group %0;\n" :: "n"(N) : "memory")

__device__ __forceinline__ void ldsm_x4(uint32_t& r0, uint32_t& r1, uint32_t& r2, uint32_t& r3,
                                        uint32_t addr) {
    asm volatile("ldmatrix.sync.aligned.m8n8.x4.shared.b16 {%0,%1,%2,%3}, [%4];"
                 : "=r"(r0), "=r"(r1), "=r"(r2), "=r"(r3) : "r"(addr));
}
__device__ __forceinline__ void ldsm_x4_t(uint32_t& r0, uint32_t& r1, uint32_t& r2, uint32_t& r3,
                                          uint32_t addr) {
    asm volatile("ldmatrix.sync.aligned.m8n8.x4.trans.shared.b16 {%0,%1,%2,%3}, [%4];"
                 : "=r"(r0), "=r"(r1), "=r"(r2), "=r"(r3) : "r"(addr));
}

__device__ __forceinline__ void mma_f16(float& c0, float& c1, float& c2, float& c3,
                                        uint32_t a0, uint32_t a1, uint32_t a2, uint32_t a3,
                                        uint32_t b0, uint32_t b1) {
    asm volatile(
        "mma.sync.aligned.m16n8k16.row.col.f32.f16.f16.f32 "
        "{%0,%1,%2,%3}, {%4,%5,%6,%7}, {%8,%9}, {%0,%1,%2,%3};\n"
        : "+f"(c0), "+f"(c1), "+f"(c2), "+f"(c3)
        : "r"(a0), "r"(a1), "r"(a2), "r"(a3), "r"(b0), "r"(b1));
}

// fast GELU (tanh form, ex2-based)
__device__ __forceinline__ float gelu_fast(float v) {
    float u = 0.7978845608f * (v + 0.044715f * v * v * v);
    float e;
    asm("ex2.approx.f32 %0, %1;" : "=f"(e) : "f"(u * 2.8853900817f));  // exp(2u)
    float th = 1.f - 2.f * __fdividef(1.f, e + 1.f);
    return 0.5f * v * (1.f + th);
}

// ---------------- fused fp32 -> fp16 conversion for all 4 weights ----------------
#define S_QKV (DIM * QKVN / 4)
#define S_SQ  (DIM * DIM / 4)
#define S_TOT (S_QKV + 3 * S_SQ)

__global__ void __launch_bounds__(256)
f2h_all(const float* __restrict__ w0, const float* __restrict__ w1,
        const float* __restrict__ w2, const float* __restrict__ w3,
        __half* __restrict__ o0, __half* __restrict__ o1,
        __half* __restrict__ o2, __half* __restrict__ o3) {
    int i = blockIdx.x * 256 + threadIdx.x;
    if (i >= S_TOT) return;
    const float* src; __half* dst; int j;
    if (i < S_QKV)                { src = w0; dst = o0; j = i; }
    else if (i < S_QKV + S_SQ)    { src = w1; dst = o1; j = i - S_QKV; }
    else if (i < S_QKV + 2 * S_SQ){ src = w2; dst = o2; j = i - S_QKV - S_SQ; }
    else                          { src = w3; dst = o3; j = i - S_QKV - 2 * S_SQ; }
    float4 v = ((const float4*)src)[j];
    __half2 a = __floats2half2_rn(v.x, v.y);
    __half2 b = __floats2half2_rn(v.z, v.w);
    ((uint2*)dst)[j] = make_uint2(*(uint32_t*)&a, *(uint32_t*)&b);
}

// ---------------- LayerNorm: warp per row ----------------
__global__ void __launch_bounds__(256)
ln_kernel(const float* __restrict__ x, const float* __restrict__ g,
          const float* __restrict__ b, __half* __restrict__ y) {
    int wid = threadIdx.x >> 5, lane = threadIdx.x & 31;
    int row = blockIdx.x * 8 + wid;
    const float4* xr = (const float4*)(x + (size_t)row * DIM);
    const float4* gp = (const float4*)g;
    const float4* bp = (const float4*)b;

    float4 v[6];
    float s = 0.f;
    #pragma unroll
    for (int i = 0; i < 6; i++) {
        v[i] = xr[lane + 32 * i];
        s += v[i].x + v[i].y + v[i].z + v[i].w;
    }
    #pragma unroll
    for (int o = 16; o; o >>= 1) s += __shfl_xor_sync(0xFFFFFFFFu, s, o);
    float mu = s * (1.0f / DIM);

    float vs = 0.f;
    #pragma unroll
    for (int i = 0; i < 6; i++) {
        float dx = v[i].x - mu, dy = v[i].y - mu, dz = v[i].z - mu, dw = v[i].w - mu;
        vs += dx * dx + dy * dy + dz * dz + dw * dw;
    }
    #pragma unroll
    for (int o = 16; o; o >>= 1) vs += __shfl_xor_sync(0xFFFFFFFFu, vs, o);
    float inv = rsqrtf(vs * (1.0f / DIM) + 1e-5f);

    uint2* yr = (uint2*)(y + (size_t)row * DIM);
    #pragma unroll
    for (int i = 0; i < 6; i++) {
        float4 gv = gp[lane + 32 * i];
        float4 bv = bp[lane + 32 * i];
        float o0 = (v[i].x - mu) * inv * gv.x + bv.x;
        float o1 = (v[i].y - mu) * inv * gv.y + bv.y;
        float o2 = (v[i].z - mu) * inv * gv.z + bv.z;
        float o3 = (v[i].w - mu) * inv * gv.w + bv.w;
        __half2 ha = __floats2half2_rn(o0, o1);
        __half2 hb = __floats2half2_rn(o2, o3);
        yr[lane + 32 * i] = make_uint2(*(uint32_t*)&ha, *(uint32_t*)&hb);
    }
}

// ---------------- fp16 GEMM A: 128x128 tile, 4 warps (2x2), 64x64 warp tile ----------
#define G7_AH (128 * 40)
#define G7_BH (32 * 136)
#define G7_ST ((G7_AH + G7_BH) * 2)
#define GEMM7_SMEM (3 * G7_ST)

template <int ACT, bool HAS_BIAS, bool HAS_RES, bool OUT_HALF>
__global__ void __launch_bounds__(128, 2)
gemm10(const __half* __restrict__ A, const __half* __restrict__ Bm,
       const float* __restrict__ bias, const float* __restrict__ resid,
       float* __restrict__ C, __half* __restrict__ Ch, int N, int K) {
    extern __shared__ char smc[];

    int tid = threadIdx.x;
    int wid = tid >> 5, lane = tid & 31;
    int g = lane >> 2, t4 = lane & 3;
    int wm = wid & 1, wn = wid >> 1;
    int m0 = blockIdx.y * 128, n0 = blockIdx.x * 128;
    int rb = wm * 64, cb = wn * 64;

    int a_row = lane & 15, a_kh = (lane >> 4) * 8;
    int b_k = ((lane >> 3) & 1) * 8 + (lane & 7);
    int b_n = (lane >> 4) * 8;

    float acc[4][8][4];
    #pragma unroll
    for (int i = 0; i < 4; i++)
        #pragma unroll
        for (int j = 0; j < 8; j++)
            #pragma unroll
            for (int q = 0; q < 4; q++) acc[i][j][q] = 0.f;

    auto load_stage = [&](int t, int s) {
        __half* As = (__half*)(smc + s * G7_ST);
        __half* Bs = As + G7_AH;
        int kt = t << 5;
        #pragma unroll
        for (int i = 0; i < 4; i++) {
            int ch = tid + 128 * i;
            int r = ch >> 2, c = ch & 3;
            cp16(smem_u32(&As[r * 40 + c * 8]), A + (size_t)(m0 + r) * K + kt + c * 8);
        }
        #pragma unroll
        for (int i = 0; i < 4; i++) {
            int ch = tid + 128 * i;
            int r = ch >> 4, c = ch & 15;
            cp16(smem_u32(&Bs[r * 136 + c * 8]), Bm + (size_t)(kt + r) * N + n0 + c * 8);
        }
        CP_COMMIT();
    };

    const int T = K >> 5;
    load_stage(0, 0);
    load_stage(1, 1);

    for (int t = 0; t < T; t++) {
        int s = t % 3;
        if (t + 1 < T) { CP_WAIT(1); } else { CP_WAIT(0); }
        __syncthreads();
        if (t + 2 < T) load_stage(t + 2, (t + 2) % 3);

        const __half* As = (const __half*)(smc + s * G7_ST);
        const __half* Bs = As + G7_AH;

        #pragma unroll
        for (int ks = 0; ks < 2; ks++) {
            uint32_t af[4][4];
            #pragma unroll
            for (int mi = 0; mi < 4; mi++)
                ldsm_x4(af[mi][0], af[mi][1], af[mi][2], af[mi][3],
                        smem_u32(&As[(rb + mi * 16 + a_row) * 40 + ks * 16 + a_kh]));
            uint32_t bf[8][2];
            #pragma unroll
            for (int njp = 0; njp < 4; njp++)
                ldsm_x4_t(bf[njp * 2][0], bf[njp * 2][1], bf[njp * 2 + 1][0], bf[njp * 2 + 1][1],
                          smem_u32(&Bs[(ks * 16 + b_k) * 136 + cb + njp * 16 + b_n]));
            #pragma unroll
            for (int mi = 0; mi < 4; mi++)
                #pragma unroll
                for (int nj = 0; nj < 8; nj++)
                    mma_f16(acc[mi][nj][0], acc[mi][nj][1], acc[mi][nj][2], acc[mi][nj][3],
                            af[mi][0], af[mi][1], af[mi][2], af[mi][3],
                            bf[nj][0], bf[nj][1]);
        }
    }

    #pragma unroll
    for (int mi = 0; mi < 4; mi++) {
        #pragma unroll
        for (int half_ = 0; half_ < 2; half_++) {
            int r = m0 + rb + mi * 16 + half_ * 8 + g;
            const float* rrow = HAS_RES ? resid + (size_t)r * N : nullptr;
            #pragma unroll
            for (int nj = 0; nj < 8; nj++) {
                int c = n0 + cb + nj * 8 + t4 * 2;
                float v0 = acc[mi][nj][half_ * 2 + 0];
                float v1 = acc[mi][nj][half_ * 2 + 1];
                if (HAS_BIAS) { v0 += bias[c]; v1 += bias[c + 1]; }
                if (HAS_RES)  { v0 += rrow[c]; v1 += rrow[c + 1]; }
                if (ACT == 1) { v0 = gelu_fast(v0); v1 = gelu_fast(v1); }
                if (OUT_HALF) {
                    __half2 hv = __floats2half2_rn(v0, v1);
                    *(uint32_t*)(Ch + (size_t)r * N + c) = *(uint32_t*)&hv;
                } else {
                    *(float2*)(C + (size_t)r * N + c) = make_float2(v0, v1);
                }
            }
        }
    }
}

// ---------------- fp16 GEMM B: 128x64 tile, 4 warps (2x2), 64x32 warp tile, 3 CTA/SM ----
#define GN_AH (128 * 40)
#define GN_BH (32 * 72)
#define GN_ST ((GN_AH + GN_BH) * 2)
#define GEMMN64_SMEM (3 * GN_ST)

template <int ACT, bool HAS_BIAS, bool HAS_RES, bool OUT_HALF>
__global__ void __launch_bounds__(128, 3)
gemm_n64(const __half* __restrict__ A, const __half* __restrict__ Bm,
         const float* __restrict__ bias, const float* __restrict__ resid,
         float* __restrict__ C, __half* __restrict__ Ch, int N, int K) {
    extern __shared__ char smc[];

    int tid = threadIdx.x;
    int wid = tid >> 5, lane = tid & 31;
    int g = lane >> 2, t4 = lane & 3;
    int wm = wid & 1, wn = wid >> 1;
    int m0 = blockIdx.y * 128, n0 = blockIdx.x * 64;
    int rb = wm * 64, cb = wn * 32;

    int a_row = lane & 15, a_kh = (lane >> 4) * 8;
    int b_k = ((lane >> 3) & 1) * 8 + (lane & 7);
    int b_n = (lane >> 4) * 8;

    float acc[4][4][4];
    #pragma unroll
    for (int i = 0; i < 4; i++)
        #pragma unroll
        for (int j = 0; j < 4; j++)
            #pragma unroll
            for (int q = 0; q < 4; q++) acc[i][j][q] = 0.f;

    auto load_stage = [&](int t, int s) {
        __half* As = (__half*)(smc + s * GN_ST);
        __half* Bs = As + GN_AH;
        int kt = t << 5;
        #pragma unroll
        for (int i = 0; i < 4; i++) {
            int ch = tid + 128 * i;
            int r = ch >> 2, c = ch & 3;
            cp16(smem_u32(&As[r * 40 + c * 8]), A + (size_t)(m0 + r) * K + kt + c * 8);
        }
        #pragma unroll
        for (int i = 0; i < 2; i++) {
            int ch = tid + 128 * i;
            int r = ch >> 3, c = ch & 7;
            cp16(smem_u32(&Bs[r * 72 + c * 8]), Bm + (size_t)(kt + r) * N + n0 + c * 8);
        }
        CP_COMMIT();
    };

    const int T = K >> 5;
    load_stage(0, 0);
    load_stage(1, 1);

    for (int t = 0; t < T; t++) {
        int s = t % 3;
        if (t + 1 < T) { CP_WAIT(1); } else { CP_WAIT(0); }
        __syncthreads();
        if (t + 2 < T) load_stage(t + 2, (t + 2) % 3);

        const __half* As = (const __half*)(smc + s * GN_ST);
        const __half* Bs = As + GN_AH;

        #pragma unroll
        for (int ks = 0; ks < 2; ks++) {
            uint32_t af[4][4];
            #pragma unroll
            for (int mi = 0; mi < 4; mi++)
                ldsm_x4(af[mi][0], af[mi][1], af[mi][2], af[mi][3],
                        smem_u32(&As[(rb + mi * 16 + a_row) * 40 + ks * 16 + a_kh]));
            uint32_t bf[4][2];
            #pragma unroll
            for (int njp = 0; njp < 2; njp++)
                ldsm_x4_t(bf[njp * 2][0], bf[njp * 2][1], bf[njp * 2 + 1][0], bf[njp * 2 + 1][1],
                          smem_u32(&Bs[(ks * 16 + b_k) * 72 + cb + njp * 16 + b_n]));
            #pragma unroll
            for (int mi = 0; mi < 4; mi++)
                #pragma unroll
                for (int nj = 0; nj < 4; nj++)
                    mma_f16(acc[mi][nj][0], acc[mi][nj][1], acc[mi][nj][2], acc[mi][nj][3],
                            af[mi][0], af[mi][1], af[mi][2], af[mi][3],
                            bf[nj][0], bf[nj][1]);
        }
    }

    #pragma unroll
    for (int mi = 0; mi < 4; mi++) {
        #pragma unroll
        for (int half_ = 0; half_ < 2; half_++) {
            int r = m0 + rb + mi * 16 + half_ * 8 + g;
            const float* rrow = HAS_RES ? resid + (size_t)r * N : nullptr;
            #pragma unroll
            for (int nj = 0; nj < 4; nj++) {
                int c = n0 + cb + nj * 8 + t4 * 2;
                float v0 = acc[mi][nj][half_ * 2 + 0];
                float v1 = acc[mi][nj][half_ * 2 + 1];
                if (HAS_BIAS) { v0 += bias[c]; v1 += bias[c + 1]; }
                if (HAS_RES)  { v0 += rrow[c]; v1 += rrow[c + 1]; }
                if (ACT == 1) { v0 = gelu_fast(v0); v1 = gelu_fast(v1); }
                if (OUT_HALF) {
                    __half2 hv = __floats2half2_rn(v0, v1);
                    *(uint32_t*)(Ch + (size_t)r * N + c) = *(uint32_t*)&hv;
                } else {
                    *(float2*)(C + (size_t)r * N + c) = make_float2(v0, v1);
                }
            }
        }
    }
}

// ---------------- fp16 flash attention: 4 warps x 32 q-rows, single barrier/iter ----------
#define AK_ST 72
#define ATTN13_SMEM (2 * 64 * AK_ST * 2 * 2 + 1024 * 2)

__global__ void __launch_bounds__(128, 2)
attn13(const __half* __restrict__ qkv, const int* __restrict__ mask,
       __half* __restrict__ o_out) {
    extern __shared__ char smc[];
    __half* KsB = (__half*)smc;
    __half* VsB = KsB + 2 * 64 * AK_ST;
    __half* Mkh = VsB + 2 * 64 * AK_ST;

    int h = blockIdx.y, b = blockIdx.z;
    int tid = threadIdx.x;
    int wid = tid >> 5, lane = tid & 31;
    int g = lane >> 2, t4 = lane & 3;
    int rb0 = wid * 32;
    int qrow0 = blockIdx.x * 128;

    int kA_n = (lane >> 4) * 8 + (lane & 7);
    int kA_d = ((lane >> 3) & 1) * 8;
    int vT_k = ((lane >> 3) & 1) * 8 + (lane & 7);
    int vT_d = (lane >> 4) * 8;

    auto stage_kv = [&](int t, int s) {
        __half* Ks = KsB + s * 64 * AK_ST;
        __half* Vs = VsB + s * 64 * AK_ST;
        int kt = t * 64;
        #pragma unroll
        for (int it = 0; it < 4; it++) {
            int idx = tid + 128 * it;
            int r = idx >> 3, c = idx & 7;
            const __half* kp = qkv + (size_t)(b * NTOK + kt + r) * QKVN + DIM + h * HD + c * 8;
            cp16(smem_u32(&Ks[r * AK_ST + c * 8]), kp);
            cp16(smem_u32(&Vs[r * AK_ST + c * 8]), kp + DIM);
        }
        CP_COMMIT();
    };

    // kick off tile 0 ASAP, then overlap Q/mask loads with it
    stage_kv(0, 0);

    #pragma unroll
    for (int i = 0; i < 8; i++)
        Mkh[tid + 128 * i] = __int2half_rn(mask[b * NTOK + tid + 128 * i]);

    const __half2 C2 = __floats2half2_rn(0.18033688f, 0.18033688f);  // 0.125*log2(e)

    uint32_t qf[2][4][4];
    #pragma unroll
    for (int r = 0; r < 2; r++) {
        const uint32_t* qlo = (const uint32_t*)(qkv + (size_t)(b * NTOK + qrow0 + rb0 + r * 16 + g) * QKVN + h * HD);
        const uint32_t* qhi = (const uint32_t*)(qkv + (size_t)(b * NTOK + qrow0 + rb0 + r * 16 + g + 8) * QKVN + h * HD);
        #pragma unroll
        for (int kc = 0; kc < 4; kc++) {
            qf[r][kc][0] = qlo[kc * 8 + t4];
            qf[r][kc][1] = qhi[kc * 8 + t4];
            qf[r][kc][2] = qlo[kc * 8 + t4 + 4];
            qf[r][kc][3] = qhi[kc * 8 + t4 + 4];
        }
    }

    float oacc[2][8][4];
    #pragma unroll
    for (int r = 0; r < 2; r++)
        #pragma unroll
        for (int i = 0; i < 8; i++)
            #pragma unroll
            for (int q = 0; q < 4; q++) oacc[r][i][q] = 0.f;
    float lsum[2][2] = {{0.f, 0.f}, {0.f, 0.f}};

    const int NT = NTOK / 64;

    for (int t = 0; t < NT; t++) {
        int s = t & 1;
        // single barrier per iteration: proves slot s^1 is consumed (and at t==0
        // publishes the Mkh stores block-wide) before restaging.
        __syncthreads();
        if (t + 1 < NT) { stage_kv(t + 1, s ^ 1); CP_WAIT(1); }
        else            { CP_WAIT(0); }

        const __half* Ks = KsB + s * 64 * AK_ST;
        const __half* Vs = VsB + s * 64 * AK_ST;

        // ---- S = Q @ K^T ----
        float sc[2][8][4];
        #pragma unroll
        for (int r = 0; r < 2; r++)
            #pragma unroll
            for (int nj = 0; nj < 8; nj++)
                #pragma unroll
                for (int q = 0; q < 4; q++) sc[r][nj][q] = 0.f;
        #pragma unroll
        for (int kc = 0; kc < 4; kc++) {
            uint32_t kb[8][2];
            #pragma unroll
            for (int njp = 0; njp < 4; njp++)
                ldsm_x4(kb[njp * 2][0], kb[njp * 2][1], kb[njp * 2 + 1][0], kb[njp * 2 + 1][1],
                        smem_u32(&Ks[(njp * 16 + kA_n) * AK_ST + kc * 16 + kA_d]));
            #pragma unroll
            for (int r = 0; r < 2; r++)
                #pragma unroll
                for (int nj = 0; nj < 8; nj++)
                    mma_f16(sc[r][nj][0], sc[r][nj][1], sc[r][nj][2], sc[r][nj][3],
                            qf[r][kc][0], qf[r][kc][1], qf[r][kc][2], qf[r][kc][3],
                            kb[nj][0], kb[nj][1]);
        }

        // ---- P = ex2.f16x2(S * 0.125*log2e) * mask, in registers ----
        uint32_t pa[2][8][2];
        const __half* mkt = Mkh + t * 64;
        #pragma unroll
        for (int r = 0; r < 2; r++) {
            #pragma unroll
            for (int nj = 0; nj < 8; nj++) {
                uint32_t mkp = *(uint32_t*)&mkt[nj * 8 + 2 * t4];
                __half2 s01 = __floats2half2_rn(sc[r][nj][0], sc[r][nj][1]);
                __half2 s23 = __floats2half2_rn(sc[r][nj][2], sc[r][nj][3]);
                s01 = __hmul2(s01, C2);
                s23 = __hmul2(s23, C2);
                uint32_t e01, e23;
                asm("ex2.approx.f16x2 %0, %1;" : "=r"(e01) : "r"(*(uint32_t*)&s01));
                asm("ex2.approx.f16x2 %0, %1;" : "=r"(e23) : "r"(*(uint32_t*)&s23));
                __half2 p01 = __hmul2(*(__half2*)&e01, *(__half2*)&mkp);
                __half2 p23 = __hmul2(*(__half2*)&e23, *(__half2*)&mkp);
                float2 f01 = __half22float2(p01), f23 = __half22float2(p23);
                lsum[r][0] += f01.x + f01.y;
                lsum[r][1] += f23.x + f23.y;
                pa[r][nj][0] = *(uint32_t*)&p01;
                pa[r][nj][1] = *(uint32_t*)&p23;
            }
        }

        // ---- O += P @ V ----
        #pragma unroll
        for (int kc = 0; kc < 4; kc++) {
            uint32_t vb[8][2];
            #pragma unroll
            for (int njp = 0; njp < 4; njp++)
                ldsm_x4_t(vb[njp * 2][0], vb[njp * 2][1], vb[njp * 2 + 1][0], vb[njp * 2 + 1][1],
                          smem_u32(&Vs[(kc * 16 + vT_k) * AK_ST + njp * 16 + vT_d]));
            #pragma unroll
            for (int r = 0; r < 2; r++) {
                uint32_t a0 = pa[r][2 * kc][0],     a1 = pa[r][2 * kc][1];
                uint32_t a2 = pa[r][2 * kc + 1][0], a3 = pa[r][2 * kc + 1][1];
                #pragma unroll
                for (int nj = 0; nj < 8; nj++)
                    mma_f16(oacc[r][nj][0], oacc[r][nj][1], oacc[r][nj][2], oacc[r][nj][3],
                            a0, a1, a2, a3, vb[nj][0], vb[nj][1]);
            }
        }
    }

    #pragma unroll
    for (int r = 0; r < 2; r++) {
        float llo = lsum[r][0], lhi = lsum[r][1];
        llo += __shfl_xor_sync(0xFFFFFFFFu, llo, 1);
        llo += __shfl_xor_sync(0xFFFFFFFFu, llo, 2);
        lhi += __shfl_xor_sync(0xFFFFFFFFu, lhi, 1);
        lhi += __shfl_xor_sync(0xFFFFFFFFu, lhi, 2);
        float inv_lo = 1.0f / llo, inv_hi = 1.0f / lhi;

        __half* olo = o_out + (size_t)(b * NTOK + qrow0 + rb0 + r * 16 + g) * DIM + h * HD;
        __half* ohi = olo + (size_t)8 * DIM;
        #pragma unroll
        for (int nj = 0; nj < 8; nj++) {
            int c = nj * 8 + 2 * t4;
            __half2 va = __floats2half2_rn(oacc[r][nj][0] * inv_lo, oacc[r][nj][1] * inv_lo);
            __half2 vb2 = __floats2half2_rn(oacc[r][nj][2] * inv_hi, oacc[r][nj][3] * inv_hi);
            *(uint32_t*)(olo + c) = *(uint32_t*)&va;
            *(uint32_t*)(ohi + c) = *(uint32_t*)&vb2;
        }
    }
}

// ---------------- launcher (R14 structure: f2h_all on side stream vs LN1) ----------------
extern "C" void kernel_launch(void* const* d_in, const int* in_sizes, int n_in,
                              void* d_out, int out_size) {
    const float* x      = (const float*)d_in[0];
    const int*   mask   = (const int*)  d_in[1];
    const float* g1     = (const float*)d_in[2];
    const float* b1     = (const float*)d_in[3];
    const float* w_qkv  = (const float*)d_in[4];
    const float* w_proj = (const float*)d_in[5];
    const float* b_proj = (const float*)d_in[6];
    const float* g2     = (const float*)d_in[7];
    const float* b2     = (const float*)d_in[8];
    const float* w_fc1  = (const float*)d_in[9];
    const float* b_fc1  = (const float*)d_in[10];
    const float* w_fc2  = (const float*)d_in[11];
    const float* b_fc2  = (const float*)d_in[12];
    float* out = (float*)d_out;

    static bool init_done = false;
    static __half *h16, *qkv16, *o16, *h2_16, *a16;
    static __half *wqkv16, *wproj16, *wfc1_16, *wfc2_16;
    static float *x1_p;
    static cudaStream_t s2;
    static cudaEvent_t evA, evB;
    if (!init_done) {
        cudaGetSymbolAddress((void**)&h16, g_h16);
        cudaGetSymbolAddress((void**)&qkv16, g_qkv16);
        cudaGetSymbolAddress((void**)&o16, g_o16);
        cudaGetSymbolAddress((void**)&h2_16, g_h2_16);
        cudaGetSymbolAddress((void**)&a16, g_a16);
        cudaGetSymbolAddress((void**)&wqkv16, g_wqkv16);
        cudaGetSymbolAddress((void**)&wproj16, g_wproj16);
        cudaGetSymbolAddress((void**)&wfc1_16, g_wfc1_16);
        cudaGetSymbolAddress((void**)&wfc2_16, g_wfc2_16);
        cudaGetSymbolAddress((void**)&x1_p, g_x1);
        cudaStreamCreateWithFlags(&s2, cudaStreamNonBlocking);
        cudaEventCreateWithFlags(&evA, cudaEventDisableTiming);
        cudaEventCreateWithFlags(&evB, cudaEventDisableTiming);
        cudaFuncSetAttribute(attn13, cudaFuncAttributeMaxDynamicSharedMemorySize, ATTN13_SMEM);
        cudaFuncSetAttribute(gemm10<0, false, false, true>,
                             cudaFuncAttributeMaxDynamicSharedMemorySize, GEMM7_SMEM);
        cudaFuncSetAttribute(gemm_n64<0, true, true, false>,
                             cudaFuncAttributeMaxDynamicSharedMemorySize, GEMMN64_SMEM);
        cudaFuncSetAttribute(gemm_n64<1, true, false, true>,
                             cudaFuncAttributeMaxDynamicSharedMemorySize, GEMMN64_SMEM);
        init_done = true;
    }

    // fork: f2h_all on s2 overlaps LN1 on the main stream (R14 structure)
    cudaEventRecord(evA, 0);
    cudaStreamWaitEvent(s2, evA, 0);
    f2h_all<<<(S_TOT + 255) / 256, 256, 0, s2>>>(w_qkv, w_proj, w_fc1, w_fc2,
                                                 wqkv16, wproj16, wfc1_16, wfc2_16);
    cudaEventRecord(evB, s2);

    ln_kernel<<<MTOT / 8, 256>>>(x, g1, b1, h16);

    // join before qkv (needs weights)
    cudaStreamWaitEvent(0, evB, 0);

    gemm10<0, false, false, true><<<dim3(QKVN / 128, MTOT / 128), 128, GEMM7_SMEM>>>(
        h16, wqkv16, nullptr, nullptr, nullptr, qkv16, QKVN, DIM);

    attn13<<<dim3(NTOK / 128, HEADS, BATCH), 128, ATTN13_SMEM>>>(qkv16, mask, o16);

    gemm_n64<0, true, true, false><<<dim3(DIM / 64, MTOT / 128), 128, GEMMN64_SMEM>>>(
        o16, wproj16, b_proj, x, x1_p, nullptr, DIM, DIM);

    ln_kernel<<<MTOT / 8, 256>>>(x1_p, g2, b2, h2_16);

    gemm_n64<1, true, false, true><<<dim3(DIM / 64, MTOT / 128), 128, GEMMN64_SMEM>>>(
        h2_16, wfc1_16, b_fc1, nullptr, nullptr, a16, DIM, DIM);

    gemm_n64<0, true, true, false><<<dim3(DIM / 64, MTOT / 128), 128, GEMMN64_SMEM>>>(
        a16, wfc2_16, b_fc2, x1_p, out, nullptr, DIM, DIM);
}

// round 17
// speedup vs baseline: 1.1266x; 1.1141x over previous
#include <cuda_runtime.h>
#include <cuda_fp16.h>
#include <math.h>
#include <stdint.h>

#define BATCH 8
#define NTOK 1024
#define DIM 768
#define HEADS 12
#define HD 64
#define MTOT (BATCH * NTOK)       // 8192
#define QKVN (3 * DIM)            // 2304
#define MH (MTOT / 2)             // 4096 rows per chain
#define BHALF (BATCH / 2)         // 4 batches per chain

// ---------------- scratch ----------------
__device__ __half g_h16[MTOT * DIM];
__device__ __half g_qkv16[MTOT * QKVN];
__device__ __half g_o16[MTOT * DIM];
__device__ float  g_x1[MTOT * DIM];
__device__ __half g_h2_16[MTOT * DIM];
__device__ __half g_a16[MTOT * DIM];
__device__ __half g_wqkv16[DIM * QKVN];
__device__ __half g_wproj16[DIM * DIM];
__device__ __half g_wfc1_16[DIM * DIM];
__device__ __half g_wfc2_16[DIM * DIM];

// ---------------- helpers ----------------
__device__ __forceinline__ uint32_t smem_u32(const void* p) {
    return (uint32_t)__cvta_generic_to_shared(p);
}
__device__ __forceinline__ void cp16(uint32_t dst, const void* src) {
    asm volatile("cp.async.cg.shared.global [%0], [%1], 16;\n" :: "r"(dst), "l"(src));
}
#define CP_COMMIT()  asm volatile("cp.async.commit_group;\n" ::: "memory")
#define CP_WAIT(N)   asm volatile("cp.async.wait_group %0;\n" :: "n"(N) : "memory")

__device__ __forceinline__ void ldsm_x4(uint32_t& r0, uint32_t& r1, uint32_t& r2, uint32_t& r3,
                                        uint32_t addr) {
    asm volatile("ldmatrix.sync.aligned.m8n8.x4.shared.b16 {%0,%1,%2,%3}, [%4];"
                 : "=r"(r0), "=r"(r1), "=r"(r2), "=r"(r3) : "r"(addr));
}
__device__ __forceinline__ void ldsm_x4_t(uint32_t& r0, uint32_t& r1, uint32_t& r2, uint32_t& r3,
                                          uint32_t addr) {
    asm volatile("ldmatrix.sync.aligned.m8n8.x4.trans.shared.b16 {%0,%1,%2,%3}, [%4];"
                 : "=r"(r0), "=r"(r1), "=r"(r2), "=r"(r3) : "r"(addr));
}

__device__ __forceinline__ void mma_f16(float& c0, float& c1, float& c2, float& c3,
                                        uint32_t a0, uint32_t a1, uint32_t a2, uint32_t a3,
                                        uint32_t b0, uint32_t b1) {
    asm volatile(
        "mma.sync.aligned.m16n8k16.row.col.f32.f16.f16.f32 "
        "{%0,%1,%2,%3}, {%4,%5,%6,%7}, {%8,%9}, {%0,%1,%2,%3};\n"
        : "+f"(c0), "+f"(c1), "+f"(c2), "+f"(c3)
        : "r"(a0), "r"(a1), "r"(a2), "r"(a3), "r"(b0), "r"(b1));
}

// fast GELU (tanh form, ex2-based)
__device__ __forceinline__ float gelu_fast(float v) {
    float u = 0.7978845608f * (v + 0.044715f * v * v * v);
    float e;
    asm("ex2.approx.f32 %0, %1;" : "=f"(e) : "f"(u * 2.8853900817f));
    float th = 1.f - 2.f * __fdividef(1.f, e + 1.f);
    return 0.5f * v * (1.f + th);
}

// ---------------- fused fp32 -> fp16 conversion for all 4 weights ----------------
#define S_QKV (DIM * QKVN / 4)
#define S_SQ  (DIM * DIM / 4)
#define S_TOT (S_QKV + 3 * S_SQ)

__global__ void __launch_bounds__(256)
f2h_all(const float* __restrict__ w0, const float* __restrict__ w1,
        const float* __restrict__ w2, const float* __restrict__ w3,
        __half* __restrict__ o0, __half* __restrict__ o1,
        __half* __restrict__ o2, __half* __restrict__ o3) {
    int i = blockIdx.x * 256 + threadIdx.x;
    if (i >= S_TOT) return;
    const float* src; __half* dst; int j;
    if (i < S_QKV)                { src = w0; dst = o0; j = i; }
    else if (i < S_QKV + S_SQ)    { src = w1; dst = o1; j = i - S_QKV; }
    else if (i < S_QKV + 2 * S_SQ){ src = w2; dst = o2; j = i - S_QKV - S_SQ; }
    else                          { src = w3; dst = o3; j = i - S_QKV - 2 * S_SQ; }
    float4 v = ((const float4*)src)[j];
    __half2 a = __floats2half2_rn(v.x, v.y);
    __half2 b = __floats2half2_rn(v.z, v.w);
    ((uint2*)dst)[j] = make_uint2(*(uint32_t*)&a, *(uint32_t*)&b);
}

// ---------------- LayerNorm: warp per row ----------------
__global__ void __launch_bounds__(256)
ln_kernel(const float* __restrict__ x, const float* __restrict__ g,
          const float* __restrict__ b, __half* __restrict__ y) {
    int wid = threadIdx.x >> 5, lane = threadIdx.x & 31;
    int row = blockIdx.x * 8 + wid;
    const float4* xr = (const float4*)(x + (size_t)row * DIM);
    const float4* gp = (const float4*)g;
    const float4* bp = (const float4*)b;

    float4 v[6];
    float s = 0.f;
    #pragma unroll
    for (int i = 0; i < 6; i++) {
        v[i] = xr[lane + 32 * i];
        s += v[i].x + v[i].y + v[i].z + v[i].w;
    }
    #pragma unroll
    for (int o = 16; o; o >>= 1) s += __shfl_xor_sync(0xFFFFFFFFu, s, o);
    float mu = s * (1.0f / DIM);

    float vs = 0.f;
    #pragma unroll
    for (int i = 0; i < 6; i++) {
        float dx = v[i].x - mu, dy = v[i].y - mu, dz = v[i].z - mu, dw = v[i].w - mu;
        vs += dx * dx + dy * dy + dz * dz + dw * dw;
    }
    #pragma unroll
    for (int o = 16; o; o >>= 1) vs += __shfl_xor_sync(0xFFFFFFFFu, vs, o);
    float inv = rsqrtf(vs * (1.0f / DIM) + 1e-5f);

    uint2* yr = (uint2*)(y + (size_t)row * DIM);
    #pragma unroll
    for (int i = 0; i < 6; i++) {
        float4 gv = gp[lane + 32 * i];
        float4 bv = bp[lane + 32 * i];
        float o0 = (v[i].x - mu) * inv * gv.x + bv.x;
        float o1 = (v[i].y - mu) * inv * gv.y + bv.y;
        float o2 = (v[i].z - mu) * inv * gv.z + bv.z;
        float o3 = (v[i].w - mu) * inv * gv.w + bv.w;
        __half2 ha = __floats2half2_rn(o0, o1);
        __half2 hb = __floats2half2_rn(o2, o3);
        yr[lane + 32 * i] = make_uint2(*(uint32_t*)&ha, *(uint32_t*)&hb);
    }
}

// ---------------- fp16 GEMM A: 128x128 tile, 4 warps (2x2), 64x64 warp tile ----------
#define G7_AH (128 * 40)
#define G7_BH (32 * 136)
#define G7_ST ((G7_AH + G7_BH) * 2)
#define GEMM7_SMEM (3 * G7_ST)

template <int ACT, bool HAS_BIAS, bool HAS_RES, bool OUT_HALF>
__global__ void __launch_bounds__(128, 2)
gemm10(const __half* __restrict__ A, const __half* __restrict__ Bm,
       const float* __restrict__ bias, const float* __restrict__ resid,
       float* __restrict__ C, __half* __restrict__ Ch, int N, int K) {
    extern __shared__ char smc[];

    int tid = threadIdx.x;
    int wid = tid >> 5, lane = tid & 31;
    int g = lane >> 2, t4 = lane & 3;
    int wm = wid & 1, wn = wid >> 1;
    int m0 = blockIdx.y * 128, n0 = blockIdx.x * 128;
    int rb = wm * 64, cb = wn * 64;

    int a_row = lane & 15, a_kh = (lane >> 4) * 8;
    int b_k = ((lane >> 3) & 1) * 8 + (lane & 7);
    int b_n = (lane >> 4) * 8;

    float acc[4][8][4];
    #pragma unroll
    for (int i = 0; i < 4; i++)
        #pragma unroll
        for (int j = 0; j < 8; j++)
            #pragma unroll
            for (int q = 0; q < 4; q++) acc[i][j][q] = 0.f;

    auto load_stage = [&](int t, int s) {
        __half* As = (__half*)(smc + s * G7_ST);
        __half* Bs = As + G7_AH;
        int kt = t << 5;
        #pragma unroll
        for (int i = 0; i < 4; i++) {
            int ch = tid + 128 * i;
            int r = ch >> 2, c = ch & 3;
            cp16(smem_u32(&As[r * 40 + c * 8]), A + (size_t)(m0 + r) * K + kt + c * 8);
        }
        #pragma unroll
        for (int i = 0; i < 4; i++) {
            int ch = tid + 128 * i;
            int r = ch >> 4, c = ch & 15;
            cp16(smem_u32(&Bs[r * 136 + c * 8]), Bm + (size_t)(kt + r) * N + n0 + c * 8);
        }
        CP_COMMIT();
    };

    const int T = K >> 5;
    load_stage(0, 0);
    load_stage(1, 1);

    for (int t = 0; t < T; t++) {
        int s = t % 3;
        if (t + 1 < T) { CP_WAIT(1); } else { CP_WAIT(0); }
        __syncthreads();
        if (t + 2 < T) load_stage(t + 2, (t + 2) % 3);

        const __half* As = (const __half*)(smc + s * G7_ST);
        const __half* Bs = As + G7_AH;

        #pragma unroll
        for (int ks = 0; ks < 2; ks++) {
            uint32_t af[4][4];
            #pragma unroll
            for (int mi = 0; mi < 4; mi++)
                ldsm_x4(af[mi][0], af[mi][1], af[mi][2], af[mi][3],
                        smem_u32(&As[(rb + mi * 16 + a_row) * 40 + ks * 16 + a_kh]));
            uint32_t bf[8][2];
            #pragma unroll
            for (int njp = 0; njp < 4; njp++)
                ldsm_x4_t(bf[njp * 2][0], bf[njp * 2][1], bf[njp * 2 + 1][0], bf[njp * 2 + 1][1],
                          smem_u32(&Bs[(ks * 16 + b_k) * 136 + cb + njp * 16 + b_n]));
            #pragma unroll
            for (int mi = 0; mi < 4; mi++)
                #pragma unroll
                for (int nj = 0; nj < 8; nj++)
                    mma_f16(acc[mi][nj][0], acc[mi][nj][1], acc[mi][nj][2], acc[mi][nj][3],
                            af[mi][0], af[mi][1], af[mi][2], af[mi][3],
                            bf[nj][0], bf[nj][1]);
        }
    }

    #pragma unroll
    for (int mi = 0; mi < 4; mi++) {
        #pragma unroll
        for (int half_ = 0; half_ < 2; half_++) {
            int r = m0 + rb + mi * 16 + half_ * 8 + g;
            const float* rrow = HAS_RES ? resid + (size_t)r * N : nullptr;
            #pragma unroll
            for (int nj = 0; nj < 8; nj++) {
                int c = n0 + cb + nj * 8 + t4 * 2;
                float v0 = acc[mi][nj][half_ * 2 + 0];
                float v1 = acc[mi][nj][half_ * 2 + 1];
                if (HAS_BIAS) { v0 += bias[c]; v1 += bias[c + 1]; }
                if (HAS_RES)  { v0 += rrow[c]; v1 += rrow[c + 1]; }
                if (ACT == 1) { v0 = gelu_fast(v0); v1 = gelu_fast(v1); }
                if (OUT_HALF) {
                    __half2 hv = __floats2half2_rn(v0, v1);
                    *(uint32_t*)(Ch + (size_t)r * N + c) = *(uint32_t*)&hv;
                } else {
                    *(float2*)(C + (size_t)r * N + c) = make_float2(v0, v1);
                }
            }
        }
    }
}

// ---------------- fp16 GEMM B: 128x64 tile, 4 warps (2x2), 64x32 warp tile, 3 CTA/SM ----
#define GN_AH (128 * 40)
#define GN_BH (32 * 72)
#define GN_ST ((GN_AH + GN_BH) * 2)
#define GEMMN64_SMEM (3 * GN_ST)

template <int ACT, bool HAS_BIAS, bool HAS_RES, bool OUT_HALF>
__global__ void __launch_bounds__(128, 3)
gemm_n64(const __half* __restrict__ A, const __half* __restrict__ Bm,
         const float* __restrict__ bias, const float* __restrict__ resid,
         float* __restrict__ C, __half* __restrict__ Ch, int N, int K) {
    extern __shared__ char smc[];

    int tid = threadIdx.x;
    int wid = tid >> 5, lane = tid & 31;
    int g = lane >> 2, t4 = lane & 3;
    int wm = wid & 1, wn = wid >> 1;
    int m0 = blockIdx.y * 128, n0 = blockIdx.x * 64;
    int rb = wm * 64, cb = wn * 32;

    int a_row = lane & 15, a_kh = (lane >> 4) * 8;
    int b_k = ((lane >> 3) & 1) * 8 + (lane & 7);
    int b_n = (lane >> 4) * 8;

    float acc[4][4][4];
    #pragma unroll
    for (int i = 0; i < 4; i++)
        #pragma unroll
        for (int j = 0; j < 4; j++)
            #pragma unroll
            for (int q = 0; q < 4; q++) acc[i][j][q] = 0.f;

    auto load_stage = [&](int t, int s) {
        __half* As = (__half*)(smc + s * GN_ST);
        __half* Bs = As + GN_AH;
        int kt = t << 5;
        #pragma unroll
        for (int i = 0; i < 4; i++) {
            int ch = tid + 128 * i;
            int r = ch >> 2, c = ch & 3;
            cp16(smem_u32(&As[r * 40 + c * 8]), A + (size_t)(m0 + r) * K + kt + c * 8);
        }
        #pragma unroll
        for (int i = 0; i < 2; i++) {
            int ch = tid + 128 * i;
            int r = ch >> 3, c = ch & 7;
            cp16(smem_u32(&Bs[r * 72 + c * 8]), Bm + (size_t)(kt + r) * N + n0 + c * 8);
        }
        CP_COMMIT();
    };

    const int T = K >> 5;
    load_stage(0, 0);
    load_stage(1, 1);

    for (int t = 0; t < T; t++) {
        int s = t % 3;
        if (t + 1 < T) { CP_WAIT(1); } else { CP_WAIT(0); }
        __syncthreads();
        if (t + 2 < T) load_stage(t + 2, (t + 2) % 3);

        const __half* As = (const __half*)(smc + s * GN_ST);
        const __half* Bs = As + GN_AH;

        #pragma unroll
        for (int ks = 0; ks < 2; ks++) {
            uint32_t af[4][4];
            #pragma unroll
            for (int mi = 0; mi < 4; mi++)
                ldsm_x4(af[mi][0], af[mi][1], af[mi][2], af[mi][3],
                        smem_u32(&As[(rb + mi * 16 + a_row) * 40 + ks * 16 + a_kh]));
            uint32_t bf[4][2];
            #pragma unroll
            for (int njp = 0; njp < 2; njp++)
                ldsm_x4_t(bf[njp * 2][0], bf[njp * 2][1], bf[njp * 2 + 1][0], bf[njp * 2 + 1][1],
                          smem_u32(&Bs[(ks * 16 + b_k) * 72 + cb + njp * 16 + b_n]));
            #pragma unroll
            for (int mi = 0; mi < 4; mi++)
                #pragma unroll
                for (int nj = 0; nj < 4; nj++)
                    mma_f16(acc[mi][nj][0], acc[mi][nj][1], acc[mi][nj][2], acc[mi][nj][3],
                            af[mi][0], af[mi][1], af[mi][2], af[mi][3],
                            bf[nj][0], bf[nj][1]);
        }
    }

    #pragma unroll
    for (int mi = 0; mi < 4; mi++) {
        #pragma unroll
        for (int half_ = 0; half_ < 2; half_++) {
            int r = m0 + rb + mi * 16 + half_ * 8 + g;
            const float* rrow = HAS_RES ? resid + (size_t)r * N : nullptr;
            #pragma unroll
            for (int nj = 0; nj < 4; nj++) {
                int c = n0 + cb + nj * 8 + t4 * 2;
                float v0 = acc[mi][nj][half_ * 2 + 0];
                float v1 = acc[mi][nj][half_ * 2 + 1];
                if (HAS_BIAS) { v0 += bias[c]; v1 += bias[c + 1]; }
                if (HAS_RES)  { v0 += rrow[c]; v1 += rrow[c + 1]; }
                if (ACT == 1) { v0 = gelu_fast(v0); v1 = gelu_fast(v1); }
                if (OUT_HALF) {
                    __half2 hv = __floats2half2_rn(v0, v1);
                    *(uint32_t*)(Ch + (size_t)r * N + c) = *(uint32_t*)&hv;
                } else {
                    *(float2*)(C + (size_t)r * N + c) = make_float2(v0, v1);
                }
            }
        }
    }
}

// ---------------- fp16 flash attention: 4 warps x 32 q-rows, single barrier/iter ----------
#define AK_ST 72
#define ATTN13_SMEM (2 * 64 * AK_ST * 2 * 2 + 1024 * 2)

__global__ void __launch_bounds__(128, 2)
attn13(const __half* __restrict__ qkv, const int* __restrict__ mask,
       __half* __restrict__ o_out) {
    extern __shared__ char smc[];
    __half* KsB = (__half*)smc;
    __half* VsB = KsB + 2 * 64 * AK_ST;
    __half* Mkh = VsB + 2 * 64 * AK_ST;

    int h = blockIdx.y, b = blockIdx.z;
    int tid = threadIdx.x;
    int wid = tid >> 5, lane = tid & 31;
    int g = lane >> 2, t4 = lane & 3;
    int rb0 = wid * 32;
    int qrow0 = blockIdx.x * 128;

    int kA_n = (lane >> 4) * 8 + (lane & 7);
    int kA_d = ((lane >> 3) & 1) * 8;
    int vT_k = ((lane >> 3) & 1) * 8 + (lane & 7);
    int vT_d = (lane >> 4) * 8;

    auto stage_kv = [&](int t, int s) {
        __half* Ks = KsB + s * 64 * AK_ST;
        __half* Vs = VsB + s * 64 * AK_ST;
        int kt = t * 64;
        #pragma unroll
        for (int it = 0; it < 4; it++) {
            int idx = tid + 128 * it;
            int r = idx >> 3, c = idx & 7;
            const __half* kp = qkv + (size_t)(b * NTOK + kt + r) * QKVN + DIM + h * HD + c * 8;
            cp16(smem_u32(&Ks[r * AK_ST + c * 8]), kp);
            cp16(smem_u32(&Vs[r * AK_ST + c * 8]), kp + DIM);
        }
        CP_COMMIT();
    };

    stage_kv(0, 0);

    #pragma unroll
    for (int i = 0; i < 8; i++)
        Mkh[tid + 128 * i] = __int2half_rn(mask[b * NTOK + tid + 128 * i]);

    const __half2 C2 = __floats2half2_rn(0.18033688f, 0.18033688f);

    uint32_t qf[2][4][4];
    #pragma unroll
    for (int r = 0; r < 2; r++) {
        const uint32_t* qlo = (const uint32_t*)(qkv + (size_t)(b * NTOK + qrow0 + rb0 + r * 16 + g) * QKVN + h * HD);
        const uint32_t* qhi = (const uint32_t*)(qkv + (size_t)(b * NTOK + qrow0 + rb0 + r * 16 + g + 8) * QKVN + h * HD);
        #pragma unroll
        for (int kc = 0; kc < 4; kc++) {
            qf[r][kc][0] = qlo[kc * 8 + t4];
            qf[r][kc][1] = qhi[kc * 8 + t4];
            qf[r][kc][2] = qlo[kc * 8 + t4 + 4];
            qf[r][kc][3] = qhi[kc * 8 + t4 + 4];
        }
    }

    float oacc[2][8][4];
    #pragma unroll
    for (int r = 0; r < 2; r++)
        #pragma unroll
        for (int i = 0; i < 8; i++)
            #pragma unroll
            for (int q = 0; q < 4; q++) oacc[r][i][q] = 0.f;
    float lsum[2][2] = {{0.f, 0.f}, {0.f, 0.f}};

    const int NT = NTOK / 64;

    for (int t = 0; t < NT; t++) {
        int s = t & 1;
        __syncthreads();
        if (t + 1 < NT) { stage_kv(t + 1, s ^ 1); CP_WAIT(1); }
        else            { CP_WAIT(0); }

        const __half* Ks = KsB + s * 64 * AK_ST;
        const __half* Vs = VsB + s * 64 * AK_ST;

        float sc[2][8][4];
        #pragma unroll
        for (int r = 0; r < 2; r++)
            #pragma unroll
            for (int nj = 0; nj < 8; nj++)
                #pragma unroll
                for (int q = 0; q < 4; q++) sc[r][nj][q] = 0.f;
        #pragma unroll
        for (int kc = 0; kc < 4; kc++) {
            uint32_t kb[8][2];
            #pragma unroll
            for (int njp = 0; njp < 4; njp++)
                ldsm_x4(kb[njp * 2][0], kb[njp * 2][1], kb[njp * 2 + 1][0], kb[njp * 2 + 1][1],
                        smem_u32(&Ks[(njp * 16 + kA_n) * AK_ST + kc * 16 + kA_d]));
            #pragma unroll
            for (int r = 0; r < 2; r++)
                #pragma unroll
                for (int nj = 0; nj < 8; nj++)
                    mma_f16(sc[r][nj][0], sc[r][nj][1], sc[r][nj][2], sc[r][nj][3],
                            qf[r][kc][0], qf[r][kc][1], qf[r][kc][2], qf[r][kc][3],
                            kb[nj][0], kb[nj][1]);
        }

        uint32_t pa[2][8][2];
        const __half* mkt = Mkh + t * 64;
        #pragma unroll
        for (int r = 0; r < 2; r++) {
            #pragma unroll
            for (int nj = 0; nj < 8; nj++) {
                uint32_t mkp = *(uint32_t*)&mkt[nj * 8 + 2 * t4];
                __half2 s01 = __floats2half2_rn(sc[r][nj][0], sc[r][nj][1]);
                __half2 s23 = __floats2half2_rn(sc[r][nj][2], sc[r][nj][3]);
                s01 = __hmul2(s01, C2);
                s23 = __hmul2(s23, C2);
                uint32_t e01, e23;
                asm("ex2.approx.f16x2 %0, %1;" : "=r"(e01) : "r"(*(uint32_t*)&s01));
                asm("ex2.approx.f16x2 %0, %1;" : "=r"(e23) : "r"(*(uint32_t*)&s23));
                __half2 p01 = __hmul2(*(__half2*)&e01, *(__half2*)&mkp);
                __half2 p23 = __hmul2(*(__half2*)&e23, *(__half2*)&mkp);
                float2 f01 = __half22float2(p01), f23 = __half22float2(p23);
                lsum[r][0] += f01.x + f01.y;
                lsum[r][1] += f23.x + f23.y;
                pa[r][nj][0] = *(uint32_t*)&p01;
                pa[r][nj][1] = *(uint32_t*)&p23;
            }
        }

        #pragma unroll
        for (int kc = 0; kc < 4; kc++) {
            uint32_t vb[8][2];
            #pragma unroll
            for (int njp = 0; njp < 4; njp++)
                ldsm_x4_t(vb[njp * 2][0], vb[njp * 2][1], vb[njp * 2 + 1][0], vb[njp * 2 + 1][1],
                          smem_u32(&Vs[(kc * 16 + vT_k) * AK_ST + njp * 16 + vT_d]));
            #pragma unroll
            for (int r = 0; r < 2; r++) {
                uint32_t a0 = pa[r][2 * kc][0],     a1 = pa[r][2 * kc][1];
                uint32_t a2 = pa[r][2 * kc + 1][0], a3 = pa[r][2 * kc + 1][1];
                #pragma unroll
                for (int nj = 0; nj < 8; nj++)
                    mma_f16(oacc[r][nj][0], oacc[r][nj][1], oacc[r][nj][2], oacc[r][nj][3],
                            a0, a1, a2, a3, vb[nj][0], vb[nj][1]);
            }
        }
    }

    #pragma unroll
    for (int r = 0; r < 2; r++) {
        float llo = lsum[r][0], lhi = lsum[r][1];
        llo += __shfl_xor_sync(0xFFFFFFFFu, llo, 1);
        llo += __shfl_xor_sync(0xFFFFFFFFu, llo, 2);
        lhi += __shfl_xor_sync(0xFFFFFFFFu, lhi, 1);
        lhi += __shfl_xor_sync(0xFFFFFFFFu, lhi, 2);
        float inv_lo = 1.0f / llo, inv_hi = 1.0f / lhi;

        __half* olo = o_out + (size_t)(b * NTOK + qrow0 + rb0 + r * 16 + g) * DIM + h * HD;
        __half* ohi = olo + (size_t)8 * DIM;
        #pragma unroll
        for (int nj = 0; nj < 8; nj++) {
            int c = nj * 8 + 2 * t4;
            __half2 va = __floats2half2_rn(oacc[r][nj][0] * inv_lo, oacc[r][nj][1] * inv_lo);
            __half2 vb2 = __floats2half2_rn(oacc[r][nj][2] * inv_hi, oacc[r][nj][3] * inv_hi);
            *(uint32_t*)(olo + c) = *(uint32_t*)&va;
            *(uint32_t*)(ohi + c) = *(uint32_t*)&vb2;
        }
    }
}

// ---------------- launcher: two independent half-batch pipelines ----------------
extern "C" void kernel_launch(void* const* d_in, const int* in_sizes, int n_in,
                              void* d_out, int out_size) {
    const float* x      = (const float*)d_in[0];
    const int*   mask   = (const int*)  d_in[1];
    const float* g1     = (const float*)d_in[2];
    const float* b1     = (const float*)d_in[3];
    const float* w_qkv  = (const float*)d_in[4];
    const float* w_proj = (const float*)d_in[5];
    const float* b_proj = (const float*)d_in[6];
    const float* g2     = (const float*)d_in[7];
    const float* b2     = (const float*)d_in[8];
    const float* w_fc1  = (const float*)d_in[9];
    const float* b_fc1  = (const float*)d_in[10];
    const float* w_fc2  = (const float*)d_in[11];
    const float* b_fc2  = (const float*)d_in[12];
    float* out = (float*)d_out;

    static bool init_done = false;
    static __half *h16, *qkv16, *o16, *h2_16, *a16;
    static __half *wqkv16, *wproj16, *wfc1_16, *wfc2_16;
    static float *x1_p;
    static cudaStream_t s2;
    static cudaEvent_t ev0, evW, evEnd;
    if (!init_done) {
        cudaGetSymbolAddress((void**)&h16, g_h16);
        cudaGetSymbolAddress((void**)&qkv16, g_qkv16);
        cudaGetSymbolAddress((void**)&o16, g_o16);
        cudaGetSymbolAddress((void**)&h2_16, g_h2_16);
        cudaGetSymbolAddress((void**)&a16, g_a16);
        cudaGetSymbolAddress((void**)&wqkv16, g_wqkv16);
        cudaGetSymbolAddress((void**)&wproj16, g_wproj16);
        cudaGetSymbolAddress((void**)&wfc1_16, g_wfc1_16);
        cudaGetSymbolAddress((void**)&wfc2_16, g_wfc2_16);
        cudaGetSymbolAddress((void**)&x1_p, g_x1);
        cudaStreamCreateWithFlags(&s2, cudaStreamNonBlocking);
        cudaEventCreateWithFlags(&ev0, cudaEventDisableTiming);
        cudaEventCreateWithFlags(&evW, cudaEventDisableTiming);
        cudaEventCreateWithFlags(&evEnd, cudaEventDisableTiming);
        cudaFuncSetAttribute(attn13, cudaFuncAttributeMaxDynamicSharedMemorySize, ATTN13_SMEM);
        cudaFuncSetAttribute(gemm10<0, false, false, true>,
                             cudaFuncAttributeMaxDynamicSharedMemorySize, GEMM7_SMEM);
        cudaFuncSetAttribute(gemm_n64<0, true, true, false>,
                             cudaFuncAttributeMaxDynamicSharedMemorySize, GEMMN64_SMEM);
        cudaFuncSetAttribute(gemm_n64<1, true, false, true>,
                             cudaFuncAttributeMaxDynamicSharedMemorySize, GEMMN64_SMEM);
        init_done = true;
    }

    // chain launcher: rows [row0, row0+MH), batches [b0, b0+BHALF)
    auto chain = [&](cudaStream_t st, int row0, int b0) {
        size_t ro = (size_t)row0;
        ln_kernel<<<MH / 8, 256, 0, st>>>(x + ro * DIM, g1, b1, h16 + ro * DIM);
        gemm10<0, false, false, true><<<dim3(QKVN / 128, MH / 128), 128, GEMM7_SMEM, st>>>(
            h16 + ro * DIM, wqkv16, nullptr, nullptr, nullptr, qkv16 + ro * QKVN, QKVN, DIM);
        attn13<<<dim3(NTOK / 128, HEADS, BHALF), 128, ATTN13_SMEM, st>>>(
            qkv16 + (size_t)b0 * NTOK * QKVN, mask + b0 * NTOK,
            o16 + (size_t)b0 * NTOK * DIM);
        gemm_n64<0, true, true, false><<<dim3(DIM / 64, MH / 128), 128, GEMMN64_SMEM, st>>>(
            o16 + ro * DIM, wproj16, b_proj, x + ro * DIM, x1_p + ro * DIM, nullptr, DIM, DIM);
        ln_kernel<<<MH / 8, 256, 0, st>>>(x1_p + ro * DIM, g2, b2, h2_16 + ro * DIM);
        gemm_n64<1, true, false, true><<<dim3(DIM / 64, MH / 128), 128, GEMMN64_SMEM, st>>>(
            h2_16 + ro * DIM, wfc1_16, b_fc1, nullptr, nullptr, a16 + ro * DIM, DIM, DIM);
        gemm_n64<0, true, true, false><<<dim3(DIM / 64, MH / 128), 128, GEMMN64_SMEM, st>>>(
            a16 + ro * DIM, wfc2_16, b_fc2, x1_p + ro * DIM, out + ro * DIM, nullptr, DIM, DIM);
    };

    // fork
    cudaEventRecord(ev0, 0);
    cudaStreamWaitEvent(s2, ev0, 0);

    // weights on main stream first (chain B waits for them after its LN)
    f2h_all<<<(S_TOT + 255) / 256, 256>>>(w_qkv, w_proj, w_fc1, w_fc2,
                                          wqkv16, wproj16, wfc1_16, wfc2_16);
    cudaEventRecord(evW, 0);

    // chain B on s2: LN first (independent of weights), then wait for weights
    {
        size_t ro = (size_t)MH;
        ln_kernel<<<MH / 8, 256, 0, s2>>>(x + ro * DIM, g1, b1, h16 + ro * DIM);
        cudaStreamWaitEvent(s2, evW, 0);
        gemm10<0, false, false, true><<<dim3(QKVN / 128, MH / 128), 128, GEMM7_SMEM, s2>>>(
            h16 + ro * DIM, wqkv16, nullptr, nullptr, nullptr, qkv16 + ro * QKVN, QKVN, DIM);
        attn13<<<dim3(NTOK / 128, HEADS, BHALF), 128, ATTN13_SMEM, s2>>>(
            qkv16 + (size_t)BHALF * NTOK * QKVN, mask + BHALF * NTOK,
            o16 + (size_t)BHALF * NTOK * DIM);
        gemm_n64<0, true, true, false><<<dim3(DIM / 64, MH / 128), 128, GEMMN64_SMEM, s2>>>(
            o16 + ro * DIM, wproj16, b_proj, x + ro * DIM, x1_p + ro * DIM, nullptr, DIM, DIM);
        ln_kernel<<<MH / 8, 256, 0, s2>>>(x1_p + ro * DIM, g2, b2, h2_16 + ro * DIM);
        gemm_n64<1, true, false, true><<<dim3(DIM / 64, MH / 128), 128, GEMMN64_SMEM, s2>>>(
            h2_16 + ro * DIM, wfc1_16, b_fc1, nullptr, nullptr, a16 + ro * DIM, DIM, DIM);
        gemm_n64<0, true, true, false><<<dim3(DIM / 64, MH / 128), 128, GEMMN64_SMEM, s2>>>(
            a16 + ro * DIM, wfc2_16, b_fc2, x1_p + ro * DIM, out + ro * DIM, nullptr, DIM, DIM);
        cudaEventRecord(evEnd, s2);
    }

    // chain A on main stream (weights already ordered before it on stream 0)
    chain(0, 0, 0);

    // join
    cudaStreamWaitEvent(0, evEnd, 0);
}